// round 14
// baseline (speedup 1.0000x reference)
#include <cuda_runtime.h>
#include <cuda_bf16.h>
#include <cuda_fp16.h>
#include <math.h>
#include <stdint.h>

#define B_   2
#define S_   2048
#define H_   3072
#define NH   32
#define NKV  8
#define HD   96
#define QKV_W (NH*HD + 2*NKV*HD)   // 4608
#define M_   (B_*S_)               // 4096

// ---------------- scratch (device globals: allocation-free rule) -----------
__device__ float g_qkv[(size_t)M_ * QKV_W];
__device__ __half g_h_f16[(size_t)M_ * H_];
__device__ __half g_wq_f16[(size_t)QKV_W * H_];
__device__ __half g_wo_f16[(size_t)H_ * H_];
__device__ __half g_a_f16[(size_t)M_ * H_];
__device__ __half g_q_f16[(size_t)B_*NH*S_*HD];
__device__ __half g_k_f16[(size_t)B_*NKV*S_*HD];
__device__ __half g_v_f16[(size_t)B_*NKV*S_*HD];

// ---------------- base-target PTX helpers ----------------------------------
__device__ __forceinline__ void cp_async16(uint32_t dst, const void* src) {
    asm volatile("cp.async.cg.shared.global [%0], [%1], 16;"
                 :: "r"(dst), "l"(src) : "memory");
}
#define CP_COMMIT() asm volatile("cp.async.commit_group;" ::: "memory")
#define CP_WAIT(n)  asm volatile("cp.async.wait_group %0;" :: "n"(n) : "memory")

__device__ __forceinline__ void ldsm4(uint32_t& r0, uint32_t& r1, uint32_t& r2,
                                      uint32_t& r3, uint32_t addr) {
    asm volatile("ldmatrix.sync.aligned.m8n8.x4.shared.b16 {%0,%1,%2,%3}, [%4];"
                 : "=r"(r0), "=r"(r1), "=r"(r2), "=r"(r3) : "r"(addr));
}
__device__ __forceinline__ void ldsm4t(uint32_t& r0, uint32_t& r1, uint32_t& r2,
                                       uint32_t& r3, uint32_t addr) {
    asm volatile("ldmatrix.sync.aligned.m8n8.x4.trans.shared.b16 {%0,%1,%2,%3}, [%4];"
                 : "=r"(r0), "=r"(r1), "=r"(r2), "=r"(r3) : "r"(addr));
}
__device__ __forceinline__ void mma16816h(float* c, uint32_t a0, uint32_t a1,
                                          uint32_t a2, uint32_t a3,
                                          uint32_t b0, uint32_t b1) {
    asm volatile(
        "mma.sync.aligned.m16n8k16.row.col.f32.f16.f16.f32 "
        "{%0,%1,%2,%3}, {%4,%5,%6,%7}, {%8,%9}, {%0,%1,%2,%3};"
        : "+f"(c[0]), "+f"(c[1]), "+f"(c[2]), "+f"(c[3])
        : "r"(a0), "r"(a1), "r"(a2), "r"(a3), "r"(b0), "r"(b1));
}

__device__ __forceinline__ uint32_t pack_f16x2(float lo, float hi) {
    __half2 p = __floats2half2_rn(lo, hi);
    return *(uint32_t*)&p;
}

// ---------------------------------------------------------------------------
// fp32 -> fp16 round
// ---------------------------------------------------------------------------
__global__ void round_f16(const float* __restrict__ x, __half* __restrict__ h, int n4)
{
    int i = blockIdx.x * blockDim.x + threadIdx.x;
    if (i >= n4) return;
    float4 v = ((const float4*)x)[i];
    ((__half2*)h)[2*i]   = __floats2half2_rn(v.x, v.y);
    ((__half2*)h)[2*i+1] = __floats2half2_rn(v.z, v.w);
}

// ---------------------------------------------------------------------------
// 1-pass fp16 mma.sync GEMM (NT). 128x128 CTA tile, BK=64, 2-stage.
// 128 threads, 2x2 warps, 64x64 warp tile: 8 ldsm.x4 -> 32 mma per k-step
// (128 B/mma smem traffic, down from 192).
// ---------------------------------------------------------------------------
#define BK      64
#define LDS_    72
#define PLANE_B (128 * LDS_ * 2)      // 18432
#define BUF_B   (2 * PLANE_B)         // 36864
#define GEMM_SMEM (2 * BUF_B)         // 73728

__global__ __launch_bounds__(128, 2) void gemm_f16(
    const __half* __restrict__ A, const __half* __restrict__ Bw,
    float* __restrict__ C, int N, int K)
{
    extern __shared__ __align__(128) char smc[];
    const uint32_t sbase = (uint32_t)__cvta_generic_to_shared(smc);
    const int tid  = threadIdx.x;
    const int warp = tid >> 5, lane = tid & 31;
    const int bm = blockIdx.y * 128, bn = blockIdx.x * 128;
    const int wm = (warp >> 1) * 64;      // 0 or 64
    const int wn = (warp & 1) * 64;       // 0 or 64

    const __half* srcs[2] = { A + (size_t)bm * K, Bw + (size_t)bn * K };

    const int nch = K / BK;

    auto load_chunk = [&](int kc, int bb) {
        uint32_t sb = sbase + bb * BUF_B;
        #pragma unroll
        for (int p = 0; p < 2; p++) {
            const __half* sp = srcs[p] + kc * BK;
            uint32_t pb = sb + p * PLANE_B;
            #pragma unroll
            for (int t = 0; t < 8; t++) {
                int f = tid + t * 128;        // 0..1023
                int r = f >> 3, j = f & 7;    // row 0..127, 16B chunk 0..7
                cp_async16(pb + r * (LDS_ * 2) + j * 16,
                           sp + (size_t)r * K + j * 8);
            }
        }
        CP_COMMIT();
    };

    float c[4][8][4];
    #pragma unroll
    for (int i = 0; i < 4; i++)
        #pragma unroll
        for (int j = 0; j < 8; j++)
            #pragma unroll
            for (int q = 0; q < 4; q++) c[i][j][q] = 0.f;

    load_chunk(0, 0);

    const int arow = lane & 15;
    const int ak8  = (lane >> 4) * 8;
    const int brow = (lane & 7) + ((lane >> 4) << 3);
    const int bk8  = ((lane >> 3) & 1) * 8;

    #pragma unroll 1
    for (int kc = 0; kc < nch; kc++) {
        const int bb = kc & 1;
        CP_WAIT(0);
        __syncthreads();
        if (kc + 1 < nch) load_chunk(kc + 1, bb ^ 1);

        const uint32_t sA = sbase + bb * BUF_B;
        const uint32_t sB = sA + PLANE_B;

        #pragma unroll
        for (int ks = 0; ks < 4; ks++) {
            const int k0 = ks * 16;
            // B fragments: 8 n8-tiles (64 cols) = 4 ldsm.x4
            uint32_t bh[8][2];
            #pragma unroll
            for (int tp = 0; tp < 4; tp++) {
                uint32_t off = (uint32_t)((wn + tp*16 + brow) * LDS_ + k0 + bk8) * 2;
                ldsm4(bh[tp*2][0], bh[tp*2][1], bh[tp*2+1][0], bh[tp*2+1][1], sB + off);
            }
            // A fragments streamed per 16-row block: 8 mmas each
            #pragma unroll
            for (int ti = 0; ti < 4; ti++) {
                uint32_t off = (uint32_t)((wm + ti*16 + arow) * LDS_ + k0 + ak8) * 2;
                uint32_t ah[4];
                ldsm4(ah[0], ah[1], ah[2], ah[3], sA + off);
                #pragma unroll
                for (int tj = 0; tj < 8; tj++)
                    mma16816h(c[ti][tj], ah[0], ah[1], ah[2], ah[3],
                              bh[tj][0], bh[tj][1]);
            }
        }
    }

    const int cr = lane >> 2, cc = (lane & 3) * 2;
    #pragma unroll
    for (int ti = 0; ti < 4; ti++) {
        #pragma unroll
        for (int tj = 0; tj < 8; tj++) {
            int r0 = bm + wm + ti*16 + cr;
            int col = bn + wn + tj*8 + cc;
            *(float2*)(C + (size_t)r0 * N + col)       = make_float2(c[ti][tj][0], c[ti][tj][1]);
            *(float2*)(C + (size_t)(r0 + 8) * N + col) = make_float2(c[ti][tj][2], c[ti][tj][3]);
        }
    }
}

// ---------------------------------------------------------------------------
// RoPE: Q -> fp16 plane (scale folded), K -> fp16 plane.
// ---------------------------------------------------------------------------
__global__ void rope_split(const float* __restrict__ qkv,
                           __half* __restrict__ qf, __half* __restrict__ kf)
{
    const int total = B_ * S_ * (NH + NKV) * (HD / 2);
    int i = blockIdx.x * blockDim.x + threadIdx.x;
    if (i >= total) return;
    int d    = i % (HD/2);
    int t    = i / (HD/2);
    int head = t % (NH + NKV);
    int bs   = t / (NH + NKV);
    int b    = bs / S_;
    int s    = bs % S_;

    float inv = expf(-(float)d * (logf(10000.0f) / 48.0f));
    float ang = (float)s * inv;
    float sn, cs;
    sincosf(ang, &sn, &cs);

    const float* base = qkv + (size_t)bs * QKV_W + head * HD;
    float x1 = base[d];
    float x2 = base[d + 48];
    float y1 = x1 * cs - x2 * sn;
    float y2 = x2 * cs + x1 * sn;

    if (head < NH) {
        const float scale = 0.10206207261596577f;
        y1 *= scale; y2 *= scale;
        size_t idx = ((size_t)(b * NH + head) * S_ + s) * HD;
        qf[idx + d]      = __float2half_rn(y1);
        qf[idx + d + 48] = __float2half_rn(y2);
    } else {
        size_t idx = ((size_t)(b * NKV + (head - NH)) * S_ + s) * HD;
        kf[idx + d]      = __float2half_rn(y1);
        kf[idx + d + 48] = __float2half_rn(y2);
    }
}

// V: round to head-major fp16 plane.
__global__ void v_round(const float* __restrict__ qkv, __half* __restrict__ vf)
{
    const int total = B_ * S_ * NKV * (HD / 4);
    int i = blockIdx.x * blockDim.x + threadIdx.x;
    if (i >= total) return;
    int d4  = i % (HD/4);
    int t   = i / (HD/4);
    int kvh = t % NKV;
    int bs  = t / NKV;
    int b   = bs / S_;
    int s   = bs % S_;

    const float* src = qkv + (size_t)bs * QKV_W + NH*HD + NKV*HD + kvh*HD + d4*4;
    float4 v = *(const float4*)src;
    size_t idx = ((size_t)(b * NKV + kvh) * S_ + s) * HD + d4*4;
    *(__half2*)(vf + idx)     = __floats2half2_rn(v.x, v.y);
    *(__half2*)(vf + idx + 2) = __floats2half2_rn(v.z, v.w);
}

// ---------------------------------------------------------------------------
// Flash attention, 1-pass fp16 mma (round-13 config, unchanged).
// ---------------------------------------------------------------------------
#define ALDS   104
#define QBYTES (128 * ALDS * 2)         // 26624
#define KVTILE (64 * ALDS * 2)          // 13312
#define KVBUF  (2 * KVTILE)             // 26624
#define ASTAGES 3
#define ATT_SMEM (QBYTES + ASTAGES*KVBUF)   // 106496 -> 2 CTAs/SM

__global__ __launch_bounds__(256, 2) void attn_mma(
    const __half* __restrict__ qf, const __half* __restrict__ kf,
    const __half* __restrict__ vf, __half* __restrict__ aout)
{
    extern __shared__ __align__(128) char smc[];
    const uint32_t sb  = (uint32_t)__cvta_generic_to_shared(smc);
    const uint32_t sQ  = sb;
    const uint32_t sKV = sb + QBYTES;

    const int tid  = threadIdx.x;
    const int warp = tid >> 5, lane = tid & 31;
    const int qt = (S_/128 - 1) - blockIdx.x;   // heavy tiles first
    const int bh = blockIdx.y;
    const int b  = bh >> 5, h = bh & 31, kvh = h >> 2;
    const int q0 = qt * 128;
    const int wm = warp * 16;

    const __half* qsf = qf + ((size_t)(b*NH + h) * S_ + q0) * HD;
    const __half* ksf = kf + (size_t)(b*NKV + kvh) * S_ * HD;
    const __half* vsf = vf + (size_t)(b*NKV + kvh) * S_ * HD;

    #pragma unroll
    for (int u = 0; u < 6; u++) {
        int f = tid + u * 256;
        int r = f / 12, cidx = f % 12;
        cp_async16(sQ + r * (ALDS*2) + cidx * 16, qsf + (size_t)r * HD + cidx * 8);
    }

    auto load_kv = [&](int kt, int bb) {
        uint32_t base = sKV + bb * KVBUF;
        int k0 = kt * 64;
        #pragma unroll
        for (int u = 0; u < 3; u++) {
            int f = tid + u * 256;
            int r = f / 12, cidx = f % 12;
            size_t g = (size_t)(k0 + r) * HD + cidx * 8;
            uint32_t o = r * (ALDS*2) + cidx * 16;
            cp_async16(base + 0*KVTILE + o, ksf + g);
            cp_async16(base + 1*KVTILE + o, vsf + g);
        }
        CP_COMMIT();
    };

    const int nkt = 2 * qt + 2;
    load_kv(0, 0);
    if (nkt > 1) load_kv(1, 1); else CP_COMMIT();

    const int arow = lane & 15;
    const int ak8  = (lane >> 4) * 8;
    const int brow = (lane & 7) + ((lane >> 4) << 3);
    const int bk8  = ((lane >> 3) & 1) * 8;
    const int vrow = lane & 15;
    const int vn8  = (lane >> 4) * 8;
    const int r_   = lane >> 2;
    const int c2_  = (lane & 3) * 2;

    float o[12][4];
    #pragma unroll
    for (int t = 0; t < 12; t++)
        #pragma unroll
        for (int q = 0; q < 4; q++) o[t][q] = 0.f;
    float m0 = -1e30f, m1 = -1e30f, l0 = 0.f, l1 = 0.f;

    const int row_g0 = q0 + wm + r_;
    const int wmax   = q0 + wm + 15;

    int bb = 0;
    #pragma unroll 1
    for (int kt = 0; kt < nkt; kt++) {
        const int k0 = kt * 64;
        CP_WAIT(1);
        __syncthreads();
        if (kt + 2 < nkt) {
            int nb = bb + 2; if (nb >= ASTAGES) nb -= ASTAGES;
            load_kv(kt + 2, nb);
        } else CP_COMMIT();

        if (k0 <= wmax) {
            const uint32_t sK = sKV + bb * KVBUF;
            const uint32_t sV = sK + KVTILE;

            float s[8][4];
            #pragma unroll
            for (int t = 0; t < 8; t++)
                #pragma unroll
                for (int q = 0; q < 4; q++) s[t][q] = 0.f;

            #pragma unroll
            for (int ks = 0; ks < 6; ks++) {
                uint32_t aoff = (uint32_t)((wm + arow) * ALDS + ks*16 + ak8) * 2;
                uint32_t ah[4];
                ldsm4(ah[0], ah[1], ah[2], ah[3], sQ + aoff);
                #pragma unroll
                for (int np = 0; np < 4; np++) {
                    uint32_t boff = (uint32_t)((np*16 + brow) * ALDS + ks*16 + bk8) * 2;
                    uint32_t kh_[4];
                    ldsm4(kh_[0], kh_[1], kh_[2], kh_[3], sK + boff);
                    mma16816h(s[2*np],   ah[0],ah[1],ah[2],ah[3], kh_[0], kh_[1]);
                    mma16816h(s[2*np+1], ah[0],ah[1],ah[2],ah[3], kh_[2], kh_[3]);
                }
            }

            if (k0 + 63 > q0 + wm) {
                #pragma unroll
                for (int t = 0; t < 8; t++) {
                    int col = k0 + t*8 + c2_;
                    if (col     > row_g0)     s[t][0] = -1e30f;
                    if (col + 1 > row_g0)     s[t][1] = -1e30f;
                    if (col     > row_g0 + 8) s[t][2] = -1e30f;
                    if (col + 1 > row_g0 + 8) s[t][3] = -1e30f;
                }
            }

            float mx0 = -1e30f, mx1 = -1e30f;
            #pragma unroll
            for (int t = 0; t < 8; t++) {
                mx0 = fmaxf(mx0, fmaxf(s[t][0], s[t][1]));
                mx1 = fmaxf(mx1, fmaxf(s[t][2], s[t][3]));
            }
            mx0 = fmaxf(mx0, __shfl_xor_sync(0xffffffff, mx0, 1));
            mx0 = fmaxf(mx0, __shfl_xor_sync(0xffffffff, mx0, 2));
            mx1 = fmaxf(mx1, __shfl_xor_sync(0xffffffff, mx1, 1));
            mx1 = fmaxf(mx1, __shfl_xor_sync(0xffffffff, mx1, 2));

            float mn0 = fmaxf(m0, mx0), mn1 = fmaxf(m1, mx1);
            float al0 = __expf(m0 - mn0), al1 = __expf(m1 - mn1);
            m0 = mn0; m1 = mn1;

            float sum0 = 0.f, sum1 = 0.f;
            #pragma unroll
            for (int t = 0; t < 8; t++) {
                s[t][0] = __expf(s[t][0] - m0);
                s[t][1] = __expf(s[t][1] - m0);
                s[t][2] = __expf(s[t][2] - m1);
                s[t][3] = __expf(s[t][3] - m1);
                sum0 += s[t][0] + s[t][1];
                sum1 += s[t][2] + s[t][3];
            }
            sum0 += __shfl_xor_sync(0xffffffff, sum0, 1);
            sum0 += __shfl_xor_sync(0xffffffff, sum0, 2);
            sum1 += __shfl_xor_sync(0xffffffff, sum1, 1);
            sum1 += __shfl_xor_sync(0xffffffff, sum1, 2);
            l0 = l0 * al0 + sum0;
            l1 = l1 * al1 + sum1;

            #pragma unroll
            for (int t = 0; t < 12; t++) {
                o[t][0] *= al0; o[t][1] *= al0;
                o[t][2] *= al1; o[t][3] *= al1;
            }

            #pragma unroll
            for (int ks = 0; ks < 4; ks++) {
                const int j0 = 2*ks, j1 = 2*ks + 1;
                uint32_t ph[4];
                ph[0] = pack_f16x2(s[j0][0], s[j0][1]);
                ph[1] = pack_f16x2(s[j0][2], s[j0][3]);
                ph[2] = pack_f16x2(s[j1][0], s[j1][1]);
                ph[3] = pack_f16x2(s[j1][2], s[j1][3]);
                #pragma unroll
                for (int npp = 0; npp < 3; npp++) {
                    const int np = 2 * npp;
                    uint32_t voffa = (uint32_t)((ks*16 + vrow) * ALDS + np*16 + vn8) * 2;
                    uint32_t voffb = (uint32_t)((ks*16 + vrow) * ALDS + (np+1)*16 + vn8) * 2;
                    uint32_t vha[4], vhb[4];
                    ldsm4t(vha[0], vha[1], vha[2], vha[3], sV + voffa);
                    ldsm4t(vhb[0], vhb[1], vhb[2], vhb[3], sV + voffb);
                    mma16816h(o[2*np],   ph[0],ph[1],ph[2],ph[3], vha[0], vha[1]);
                    mma16816h(o[2*np+1], ph[0],ph[1],ph[2],ph[3], vha[2], vha[3]);
                    mma16816h(o[2*np+2], ph[0],ph[1],ph[2],ph[3], vhb[0], vhb[1]);
                    mma16816h(o[2*np+3], ph[0],ph[1],ph[2],ph[3], vhb[2], vhb[3]);
                }
            }
        }
        if (++bb == ASTAGES) bb = 0;
    }

    const float il0 = 1.f / l0, il1 = 1.f / l1;
    const size_t mrow0 = (size_t)(b * S_ + row_g0) * H_;
    const size_t mrow1 = mrow0 + 8 * (size_t)H_;
    #pragma unroll
    for (int t = 0; t < 12; t++) {
        int col = h * HD + t*8 + c2_;
        *(uint32_t*)(aout + mrow0 + col) = pack_f16x2(o[t][0]*il0, o[t][1]*il0);
        *(uint32_t*)(aout + mrow1 + col) = pack_f16x2(o[t][2]*il1, o[t][3]*il1);
    }
}

// ---------------------------------------------------------------------------

extern "C" void kernel_launch(void* const* d_in, const int* in_sizes, int n_in,
                              void* d_out, int out_size)
{
    const float* hidden = (const float*)d_in[0];
    const float* w_qkv  = (const float*)d_in[2];
    const float* w_o    = (const float*)d_in[3];
    float* out = (float*)d_out;

    float *qkv;
    __half *h_f16, *wq_f16, *wo_f16, *a_f16, *q_f16, *k_f16, *v_f16;
    cudaGetSymbolAddress((void**)&qkv,    g_qkv);
    cudaGetSymbolAddress((void**)&h_f16,  g_h_f16);
    cudaGetSymbolAddress((void**)&wq_f16, g_wq_f16);
    cudaGetSymbolAddress((void**)&wo_f16, g_wo_f16);
    cudaGetSymbolAddress((void**)&a_f16,  g_a_f16);
    cudaGetSymbolAddress((void**)&q_f16,  g_q_f16);
    cudaGetSymbolAddress((void**)&k_f16,  g_k_f16);
    cudaGetSymbolAddress((void**)&v_f16,  g_v_f16);

    cudaFuncSetAttribute(gemm_f16, cudaFuncAttributeMaxDynamicSharedMemorySize, GEMM_SMEM);
    cudaFuncSetAttribute(attn_mma, cudaFuncAttributeMaxDynamicSharedMemorySize, ATT_SMEM);

    {
        int n4;
        n4 = (M_ * H_) / 4;
        round_f16<<<(n4 + 255)/256, 256>>>(hidden, h_f16, n4);
        n4 = (QKV_W * H_) / 4;
        round_f16<<<(n4 + 255)/256, 256>>>(w_qkv, wq_f16, n4);
        n4 = (H_ * H_) / 4;
        round_f16<<<(n4 + 255)/256, 256>>>(w_o, wo_f16, n4);
    }

    gemm_f16<<<dim3(QKV_W/128, M_/128), 128, GEMM_SMEM>>>(
        h_f16, wq_f16, qkv, QKV_W, H_);

    {
        int total = B_ * S_ * (NH + NKV) * (HD/2);
        rope_split<<<(total + 255)/256, 256>>>(qkv, q_f16, k_f16);
        int vt = B_ * S_ * NKV * (HD/4);
        v_round<<<(vt + 255)/256, 256>>>(qkv, v_f16);
    }

    attn_mma<<<dim3(S_/128, B_*NH), 256, ATT_SMEM>>>(
        q_f16, k_f16, v_f16, a_f16);

    gemm_f16<<<dim3(H_/128, M_/128), 128, GEMM_SMEM>>>(
        a_f16, wo_f16, out, H_, H_);
}

// round 15
// speedup vs baseline: 1.0372x; 1.0372x over previous
#include <cuda_runtime.h>
#include <cuda_bf16.h>
#include <cuda_fp16.h>
#include <math.h>
#include <stdint.h>

#define B_   2
#define S_   2048
#define H_   3072
#define NH   32
#define NKV  8
#define HD   96
#define QKV_W (NH*HD + 2*NKV*HD)   // 4608
#define M_   (B_*S_)               // 4096

// ---------------- scratch (device globals: allocation-free rule) -----------
__device__ __half g_qkv_h[(size_t)M_ * QKV_W];   // fp16 qkv from GEMM1
__device__ __half g_h_f16[(size_t)M_ * H_];
__device__ __half g_wq_f16[(size_t)QKV_W * H_];
__device__ __half g_wo_f16[(size_t)H_ * H_];
__device__ __half g_a_f16[(size_t)M_ * H_];
__device__ __half g_q_f16[(size_t)B_*NH*S_*HD];
__device__ __half g_k_f16[(size_t)B_*NKV*S_*HD];
__device__ __half g_v_f16[(size_t)B_*NKV*S_*HD];

// ---------------- base-target PTX helpers ----------------------------------
__device__ __forceinline__ void cp_async16(uint32_t dst, const void* src) {
    asm volatile("cp.async.cg.shared.global [%0], [%1], 16;"
                 :: "r"(dst), "l"(src) : "memory");
}
#define CP_COMMIT() asm volatile("cp.async.commit_group;" ::: "memory")
#define CP_WAIT(n)  asm volatile("cp.async.wait_group %0;" :: "n"(n) : "memory")

__device__ __forceinline__ void ldsm4(uint32_t& r0, uint32_t& r1, uint32_t& r2,
                                      uint32_t& r3, uint32_t addr) {
    asm volatile("ldmatrix.sync.aligned.m8n8.x4.shared.b16 {%0,%1,%2,%3}, [%4];"
                 : "=r"(r0), "=r"(r1), "=r"(r2), "=r"(r3) : "r"(addr));
}
__device__ __forceinline__ void ldsm4t(uint32_t& r0, uint32_t& r1, uint32_t& r2,
                                       uint32_t& r3, uint32_t addr) {
    asm volatile("ldmatrix.sync.aligned.m8n8.x4.trans.shared.b16 {%0,%1,%2,%3}, [%4];"
                 : "=r"(r0), "=r"(r1), "=r"(r2), "=r"(r3) : "r"(addr));
}
__device__ __forceinline__ void mma16816h(float* c, uint32_t a0, uint32_t a1,
                                          uint32_t a2, uint32_t a3,
                                          uint32_t b0, uint32_t b1) {
    asm volatile(
        "mma.sync.aligned.m16n8k16.row.col.f32.f16.f16.f32 "
        "{%0,%1,%2,%3}, {%4,%5,%6,%7}, {%8,%9}, {%0,%1,%2,%3};"
        : "+f"(c[0]), "+f"(c[1]), "+f"(c[2]), "+f"(c[3])
        : "r"(a0), "r"(a1), "r"(a2), "r"(a3), "r"(b0), "r"(b1));
}

__device__ __forceinline__ uint32_t pack_f16x2(float lo, float hi) {
    __half2 p = __floats2half2_rn(lo, hi);
    return *(uint32_t*)&p;
}

// ---------------------------------------------------------------------------
// Fused fp32 -> fp16 rounding of all 3 tensors, one launch.
// ---------------------------------------------------------------------------
#define N4_H  ((M_ * H_) / 4)
#define N4_WQ ((QKV_W * H_) / 4)
#define N4_WO ((H_ * H_) / 4)

__global__ void round3_f16(const float* __restrict__ x0, __half* __restrict__ h0,
                           const float* __restrict__ x1, __half* __restrict__ h1,
                           const float* __restrict__ x2, __half* __restrict__ h2)
{
    int i = blockIdx.x * blockDim.x + threadIdx.x;
    const float* x; __half* h;
    if (i < N4_H)                   { x = x0; h = h0; }
    else if (i < N4_H + N4_WQ)      { x = x1; h = h1; i -= N4_H; }
    else if (i < N4_H + N4_WQ + N4_WO) { x = x2; h = h2; i -= N4_H + N4_WQ; }
    else return;
    float4 v = ((const float4*)x)[i];
    ((__half2*)h)[2*i]   = __floats2half2_rn(v.x, v.y);
    ((__half2*)h)[2*i+1] = __floats2half2_rn(v.z, v.w);
}

// ---------------------------------------------------------------------------
// 1-pass fp16 mma.sync GEMM (NT), round-13 winning config:
// 128x128 CTA tile, BK=64, 2-stage, 256 threads (2x4 warps, 64x32 warp tile),
// 2 CTAs/SM. Templated epilogue output type (float or __half).
// ---------------------------------------------------------------------------
#define BK      64
#define LDS_    72
#define PLANE_B (128 * LDS_ * 2)      // 18432
#define BUF_B   (2 * PLANE_B)         // 36864
#define GEMM_SMEM (2 * BUF_B)         // 73728

template <typename OutT>
__global__ __launch_bounds__(256, 2) void gemm_f16(
    const __half* __restrict__ A, const __half* __restrict__ Bw,
    OutT* __restrict__ C, int N, int K)
{
    extern __shared__ __align__(128) char smc[];
    const uint32_t sbase = (uint32_t)__cvta_generic_to_shared(smc);
    const int tid  = threadIdx.x;
    const int warp = tid >> 5, lane = tid & 31;
    const int bm = blockIdx.y * 128, bn = blockIdx.x * 128;
    const int wm = (warp >> 2) * 64;
    const int wn = (warp & 3) * 32;

    const __half* srcs[2] = { A + (size_t)bm * K, Bw + (size_t)bn * K };

    const int nch = K / BK;

    auto load_chunk = [&](int kc, int bb) {
        uint32_t sb = sbase + bb * BUF_B;
        #pragma unroll
        for (int p = 0; p < 2; p++) {
            const __half* sp = srcs[p] + kc * BK;
            uint32_t pb = sb + p * PLANE_B;
            #pragma unroll
            for (int t = 0; t < 4; t++) {
                int f = tid + t * 256;
                int r = f >> 3, j = f & 7;
                cp_async16(pb + r * (LDS_ * 2) + j * 16,
                           sp + (size_t)r * K + j * 8);
            }
        }
        CP_COMMIT();
    };

    float c[4][4][4];
    #pragma unroll
    for (int i = 0; i < 4; i++)
        #pragma unroll
        for (int j = 0; j < 4; j++)
            #pragma unroll
            for (int q = 0; q < 4; q++) c[i][j][q] = 0.f;

    load_chunk(0, 0);

    const int arow = lane & 15;
    const int ak8  = (lane >> 4) * 8;
    const int brow = (lane & 7) + ((lane >> 4) << 3);
    const int bk8  = ((lane >> 3) & 1) * 8;

    #pragma unroll 1
    for (int kc = 0; kc < nch; kc++) {
        const int bb = kc & 1;
        CP_WAIT(0);
        __syncthreads();
        if (kc + 1 < nch) load_chunk(kc + 1, bb ^ 1);

        const uint32_t sA = sbase + bb * BUF_B;
        const uint32_t sB = sA + PLANE_B;

        #pragma unroll
        for (int ks = 0; ks < 4; ks++) {
            const int k0 = ks * 16;
            uint32_t bh[4][2];
            #pragma unroll
            for (int tp = 0; tp < 2; tp++) {
                uint32_t off = (uint32_t)((wn + tp*16 + brow) * LDS_ + k0 + bk8) * 2;
                ldsm4(bh[tp*2][0], bh[tp*2][1], bh[tp*2+1][0], bh[tp*2+1][1], sB + off);
            }
            #pragma unroll
            for (int ti = 0; ti < 4; ti++) {
                uint32_t off = (uint32_t)((wm + ti*16 + arow) * LDS_ + k0 + ak8) * 2;
                uint32_t ah[4];
                ldsm4(ah[0], ah[1], ah[2], ah[3], sA + off);
                mma16816h(c[ti][0], ah[0], ah[1], ah[2], ah[3], bh[0][0], bh[0][1]);
                mma16816h(c[ti][1], ah[0], ah[1], ah[2], ah[3], bh[1][0], bh[1][1]);
                mma16816h(c[ti][2], ah[0], ah[1], ah[2], ah[3], bh[2][0], bh[2][1]);
                mma16816h(c[ti][3], ah[0], ah[1], ah[2], ah[3], bh[3][0], bh[3][1]);
            }
        }
    }

    const int cr = lane >> 2, cc = (lane & 3) * 2;
    #pragma unroll
    for (int ti = 0; ti < 4; ti++) {
        #pragma unroll
        for (int tj = 0; tj < 4; tj++) {
            int r0 = bm + wm + ti*16 + cr;
            int col = bn + wn + tj*8 + cc;
            if constexpr (sizeof(OutT) == 4) {
                *(float2*)((float*)C + (size_t)r0 * N + col) =
                    make_float2(c[ti][tj][0], c[ti][tj][1]);
                *(float2*)((float*)C + (size_t)(r0 + 8) * N + col) =
                    make_float2(c[ti][tj][2], c[ti][tj][3]);
            } else {
                *(uint32_t*)((__half*)C + (size_t)r0 * N + col) =
                    pack_f16x2(c[ti][tj][0], c[ti][tj][1]);
                *(uint32_t*)((__half*)C + (size_t)(r0 + 8) * N + col) =
                    pack_f16x2(c[ti][tj][2], c[ti][tj][3]);
            }
        }
    }
}

// ---------------------------------------------------------------------------
// Fused RoPE(Q,K) + V rearrange, reading fp16 qkv. One launch.
// blocks [0, NROPE): rope; blocks [NROPE, NROPE+NV): v copy.
// ---------------------------------------------------------------------------
#define ROPE_TOT (B_ * S_ * (NH + NKV) * (HD/2))
#define V_TOT    (B_ * S_ * NKV * (HD/4))

__global__ void rope_v_f16(const __half* __restrict__ qkv,
                           __half* __restrict__ qf, __half* __restrict__ kf,
                           __half* __restrict__ vf)
{
    int gi = blockIdx.x * blockDim.x + threadIdx.x;
    if (gi < ROPE_TOT) {
        int i = gi;
        int d    = i % (HD/2);
        int t    = i / (HD/2);
        int head = t % (NH + NKV);
        int bs   = t / (NH + NKV);
        int b    = bs / S_;
        int s    = bs % S_;

        float inv = expf(-(float)d * (logf(10000.0f) / 48.0f));
        float ang = (float)s * inv;
        float sn, cs;
        sincosf(ang, &sn, &cs);

        const __half* base = qkv + (size_t)bs * QKV_W + head * HD;
        float x1 = __half2float(base[d]);
        float x2 = __half2float(base[d + 48]);
        float y1 = x1 * cs - x2 * sn;
        float y2 = x2 * cs + x1 * sn;

        if (head < NH) {
            const float scale = 0.10206207261596577f;
            y1 *= scale; y2 *= scale;
            size_t idx = ((size_t)(b * NH + head) * S_ + s) * HD;
            qf[idx + d]      = __float2half_rn(y1);
            qf[idx + d + 48] = __float2half_rn(y2);
        } else {
            size_t idx = ((size_t)(b * NKV + (head - NH)) * S_ + s) * HD;
            kf[idx + d]      = __float2half_rn(y1);
            kf[idx + d + 48] = __float2half_rn(y2);
        }
    } else {
        int i = gi - ROPE_TOT;
        if (i >= V_TOT) return;
        int d4  = i % (HD/4);
        int t   = i / (HD/4);
        int kvh = t % NKV;
        int bs  = t / NKV;
        int b   = bs / S_;
        int s   = bs % S_;
        const __half* src = qkv + (size_t)bs * QKV_W + NH*HD + NKV*HD + kvh*HD + d4*4;
        size_t idx = ((size_t)(b * NKV + kvh) * S_ + s) * HD + d4*4;
        *(uint2*)(vf + idx) = *(const uint2*)src;   // 4 halves
    }
}

// ---------------------------------------------------------------------------
// Flash attention, 1-pass fp16 mma (round-13 config, unchanged).
// ---------------------------------------------------------------------------
#define ALDS   104
#define QBYTES (128 * ALDS * 2)         // 26624
#define KVTILE (64 * ALDS * 2)          // 13312
#define KVBUF  (2 * KVTILE)             // 26624
#define ASTAGES 3
#define ATT_SMEM (QBYTES + ASTAGES*KVBUF)   // 106496 -> 2 CTAs/SM

__global__ __launch_bounds__(256, 2) void attn_mma(
    const __half* __restrict__ qf, const __half* __restrict__ kf,
    const __half* __restrict__ vf, __half* __restrict__ aout)
{
    extern __shared__ __align__(128) char smc[];
    const uint32_t sb  = (uint32_t)__cvta_generic_to_shared(smc);
    const uint32_t sQ  = sb;
    const uint32_t sKV = sb + QBYTES;

    const int tid  = threadIdx.x;
    const int warp = tid >> 5, lane = tid & 31;
    const int qt = (S_/128 - 1) - blockIdx.x;   // heavy tiles first
    const int bh = blockIdx.y;
    const int b  = bh >> 5, h = bh & 31, kvh = h >> 2;
    const int q0 = qt * 128;
    const int wm = warp * 16;

    const __half* qsf = qf + ((size_t)(b*NH + h) * S_ + q0) * HD;
    const __half* ksf = kf + (size_t)(b*NKV + kvh) * S_ * HD;
    const __half* vsf = vf + (size_t)(b*NKV + kvh) * S_ * HD;

    #pragma unroll
    for (int u = 0; u < 6; u++) {
        int f = tid + u * 256;
        int r = f / 12, cidx = f % 12;
        cp_async16(sQ + r * (ALDS*2) + cidx * 16, qsf + (size_t)r * HD + cidx * 8);
    }

    auto load_kv = [&](int kt, int bb) {
        uint32_t base = sKV + bb * KVBUF;
        int k0 = kt * 64;
        #pragma unroll
        for (int u = 0; u < 3; u++) {
            int f = tid + u * 256;
            int r = f / 12, cidx = f % 12;
            size_t g = (size_t)(k0 + r) * HD + cidx * 8;
            uint32_t o = r * (ALDS*2) + cidx * 16;
            cp_async16(base + 0*KVTILE + o, ksf + g);
            cp_async16(base + 1*KVTILE + o, vsf + g);
        }
        CP_COMMIT();
    };

    const int nkt = 2 * qt + 2;
    load_kv(0, 0);
    if (nkt > 1) load_kv(1, 1); else CP_COMMIT();

    const int arow = lane & 15;
    const int ak8  = (lane >> 4) * 8;
    const int brow = (lane & 7) + ((lane >> 4) << 3);
    const int bk8  = ((lane >> 3) & 1) * 8;
    const int vrow = lane & 15;
    const int vn8  = (lane >> 4) * 8;
    const int r_   = lane >> 2;
    const int c2_  = (lane & 3) * 2;

    float o[12][4];
    #pragma unroll
    for (int t = 0; t < 12; t++)
        #pragma unroll
        for (int q = 0; q < 4; q++) o[t][q] = 0.f;
    float m0 = -1e30f, m1 = -1e30f, l0 = 0.f, l1 = 0.f;

    const int row_g0 = q0 + wm + r_;
    const int wmax   = q0 + wm + 15;

    int bb = 0;
    #pragma unroll 1
    for (int kt = 0; kt < nkt; kt++) {
        const int k0 = kt * 64;
        CP_WAIT(1);
        __syncthreads();
        if (kt + 2 < nkt) {
            int nb = bb + 2; if (nb >= ASTAGES) nb -= ASTAGES;
            load_kv(kt + 2, nb);
        } else CP_COMMIT();

        if (k0 <= wmax) {
            const uint32_t sK = sKV + bb * KVBUF;
            const uint32_t sV = sK + KVTILE;

            float s[8][4];
            #pragma unroll
            for (int t = 0; t < 8; t++)
                #pragma unroll
                for (int q = 0; q < 4; q++) s[t][q] = 0.f;

            #pragma unroll
            for (int ks = 0; ks < 6; ks++) {
                uint32_t aoff = (uint32_t)((wm + arow) * ALDS + ks*16 + ak8) * 2;
                uint32_t ah[4];
                ldsm4(ah[0], ah[1], ah[2], ah[3], sQ + aoff);
                #pragma unroll
                for (int np = 0; np < 4; np++) {
                    uint32_t boff = (uint32_t)((np*16 + brow) * ALDS + ks*16 + bk8) * 2;
                    uint32_t kh_[4];
                    ldsm4(kh_[0], kh_[1], kh_[2], kh_[3], sK + boff);
                    mma16816h(s[2*np],   ah[0],ah[1],ah[2],ah[3], kh_[0], kh_[1]);
                    mma16816h(s[2*np+1], ah[0],ah[1],ah[2],ah[3], kh_[2], kh_[3]);
                }
            }

            if (k0 + 63 > q0 + wm) {
                #pragma unroll
                for (int t = 0; t < 8; t++) {
                    int col = k0 + t*8 + c2_;
                    if (col     > row_g0)     s[t][0] = -1e30f;
                    if (col + 1 > row_g0)     s[t][1] = -1e30f;
                    if (col     > row_g0 + 8) s[t][2] = -1e30f;
                    if (col + 1 > row_g0 + 8) s[t][3] = -1e30f;
                }
            }

            float mx0 = -1e30f, mx1 = -1e30f;
            #pragma unroll
            for (int t = 0; t < 8; t++) {
                mx0 = fmaxf(mx0, fmaxf(s[t][0], s[t][1]));
                mx1 = fmaxf(mx1, fmaxf(s[t][2], s[t][3]));
            }
            mx0 = fmaxf(mx0, __shfl_xor_sync(0xffffffff, mx0, 1));
            mx0 = fmaxf(mx0, __shfl_xor_sync(0xffffffff, mx0, 2));
            mx1 = fmaxf(mx1, __shfl_xor_sync(0xffffffff, mx1, 1));
            mx1 = fmaxf(mx1, __shfl_xor_sync(0xffffffff, mx1, 2));

            float mn0 = fmaxf(m0, mx0), mn1 = fmaxf(m1, mx1);
            float al0 = __expf(m0 - mn0), al1 = __expf(m1 - mn1);
            m0 = mn0; m1 = mn1;

            float sum0 = 0.f, sum1 = 0.f;
            #pragma unroll
            for (int t = 0; t < 8; t++) {
                s[t][0] = __expf(s[t][0] - m0);
                s[t][1] = __expf(s[t][1] - m0);
                s[t][2] = __expf(s[t][2] - m1);
                s[t][3] = __expf(s[t][3] - m1);
                sum0 += s[t][0] + s[t][1];
                sum1 += s[t][2] + s[t][3];
            }
            sum0 += __shfl_xor_sync(0xffffffff, sum0, 1);
            sum0 += __shfl_xor_sync(0xffffffff, sum0, 2);
            sum1 += __shfl_xor_sync(0xffffffff, sum1, 1);
            sum1 += __shfl_xor_sync(0xffffffff, sum1, 2);
            l0 = l0 * al0 + sum0;
            l1 = l1 * al1 + sum1;

            #pragma unroll
            for (int t = 0; t < 12; t++) {
                o[t][0] *= al0; o[t][1] *= al0;
                o[t][2] *= al1; o[t][3] *= al1;
            }

            #pragma unroll
            for (int ks = 0; ks < 4; ks++) {
                const int j0 = 2*ks, j1 = 2*ks + 1;
                uint32_t ph[4];
                ph[0] = pack_f16x2(s[j0][0], s[j0][1]);
                ph[1] = pack_f16x2(s[j0][2], s[j0][3]);
                ph[2] = pack_f16x2(s[j1][0], s[j1][1]);
                ph[3] = pack_f16x2(s[j1][2], s[j1][3]);
                #pragma unroll
                for (int npp = 0; npp < 3; npp++) {
                    const int np = 2 * npp;
                    uint32_t voffa = (uint32_t)((ks*16 + vrow) * ALDS + np*16 + vn8) * 2;
                    uint32_t voffb = (uint32_t)((ks*16 + vrow) * ALDS + (np+1)*16 + vn8) * 2;
                    uint32_t vha[4], vhb[4];
                    ldsm4t(vha[0], vha[1], vha[2], vha[3], sV + voffa);
                    ldsm4t(vhb[0], vhb[1], vhb[2], vhb[3], sV + voffb);
                    mma16816h(o[2*np],   ph[0],ph[1],ph[2],ph[3], vha[0], vha[1]);
                    mma16816h(o[2*np+1], ph[0],ph[1],ph[2],ph[3], vha[2], vha[3]);
                    mma16816h(o[2*np+2], ph[0],ph[1],ph[2],ph[3], vhb[0], vhb[1]);
                    mma16816h(o[2*np+3], ph[0],ph[1],ph[2],ph[3], vhb[2], vhb[3]);
                }
            }
        }
        if (++bb == ASTAGES) bb = 0;
    }

    const float il0 = 1.f / l0, il1 = 1.f / l1;
    const size_t mrow0 = (size_t)(b * S_ + row_g0) * H_;
    const size_t mrow1 = mrow0 + 8 * (size_t)H_;
    #pragma unroll
    for (int t = 0; t < 12; t++) {
        int col = h * HD + t*8 + c2_;
        *(uint32_t*)(aout + mrow0 + col) = pack_f16x2(o[t][0]*il0, o[t][1]*il0);
        *(uint32_t*)(aout + mrow1 + col) = pack_f16x2(o[t][2]*il1, o[t][3]*il1);
    }
}

// ---------------------------------------------------------------------------

extern "C" void kernel_launch(void* const* d_in, const int* in_sizes, int n_in,
                              void* d_out, int out_size)
{
    const float* hidden = (const float*)d_in[0];
    const float* w_qkv  = (const float*)d_in[2];
    const float* w_o    = (const float*)d_in[3];
    float* out = (float*)d_out;

    __half *qkv_h, *h_f16, *wq_f16, *wo_f16, *a_f16, *q_f16, *k_f16, *v_f16;
    cudaGetSymbolAddress((void**)&qkv_h,  g_qkv_h);
    cudaGetSymbolAddress((void**)&h_f16,  g_h_f16);
    cudaGetSymbolAddress((void**)&wq_f16, g_wq_f16);
    cudaGetSymbolAddress((void**)&wo_f16, g_wo_f16);
    cudaGetSymbolAddress((void**)&a_f16,  g_a_f16);
    cudaGetSymbolAddress((void**)&q_f16,  g_q_f16);
    cudaGetSymbolAddress((void**)&k_f16,  g_k_f16);
    cudaGetSymbolAddress((void**)&v_f16,  g_v_f16);

    cudaFuncSetAttribute(gemm_f16<__half>, cudaFuncAttributeMaxDynamicSharedMemorySize, GEMM_SMEM);
    cudaFuncSetAttribute(gemm_f16<float>,  cudaFuncAttributeMaxDynamicSharedMemorySize, GEMM_SMEM);
    cudaFuncSetAttribute(attn_mma, cudaFuncAttributeMaxDynamicSharedMemorySize, ATT_SMEM);

    // 1) fused fp16 rounding of hidden + both weights (one launch)
    {
        int total = N4_H + N4_WQ + N4_WO;
        round3_f16<<<(total + 255)/256, 256>>>(hidden, h_f16, w_qkv, wq_f16,
                                               w_o, wo_f16);
    }

    // 2) QKV projection (1-pass fp16 HMMA), fp16 output
    gemm_f16<__half><<<dim3(QKV_W/128, M_/128), 256, GEMM_SMEM>>>(
        h_f16, wq_f16, qkv_h, QKV_W, H_);

    // 3) fused RoPE(Q,K) + V rearrange (one launch, fp16 in/out)
    {
        int total = ROPE_TOT + V_TOT;
        rope_v_f16<<<(total + 255)/256, 256>>>(qkv_h, q_f16, k_f16, v_f16);
    }

    // 4) causal GQA flash attention (1-pass fp16, 2 CTAs/SM)
    attn_mma<<<dim3(S_/128, B_*NH), 256, ATT_SMEM>>>(
        q_f16, k_f16, v_f16, a_f16);

    // 5) output projection (1-pass fp16 HMMA), fp32 output
    gemm_f16<float><<<dim3(H_/128, M_/128), 256, GEMM_SMEM>>>(
        a_f16, wo_f16, out, H_, H_);
}

// round 16
// speedup vs baseline: 1.0397x; 1.0023x over previous
#include <cuda_runtime.h>
#include <cuda_bf16.h>
#include <cuda_fp16.h>
#include <math.h>
#include <stdint.h>

#define B_   2
#define S_   2048
#define H_   3072
#define NH   32
#define NKV  8
#define HD   96
#define QKV_W (NH*HD + 2*NKV*HD)   // 4608
#define M_   (B_*S_)               // 4096

// ---------------- scratch (device globals: allocation-free rule) -----------
__device__ __half g_qkv_h[(size_t)M_ * QKV_W];
__device__ __half g_h_f16[(size_t)M_ * H_];
__device__ __half g_wq_f16[(size_t)QKV_W * H_];
__device__ __half g_wo_f16[(size_t)H_ * H_];
__device__ __half g_a_f16[(size_t)M_ * H_];
__device__ __half g_q_f16[(size_t)B_*NH*S_*HD];
__device__ __half g_k_f16[(size_t)B_*NKV*S_*HD];
__device__ __half g_v_f16[(size_t)B_*NKV*S_*HD];

// ---------------- base-target PTX helpers ----------------------------------
__device__ __forceinline__ void cp_async16(uint32_t dst, const void* src) {
    asm volatile("cp.async.cg.shared.global [%0], [%1], 16;"
                 :: "r"(dst), "l"(src) : "memory");
}
#define CP_COMMIT() asm volatile("cp.async.commit_group;" ::: "memory")
#define CP_WAIT(n)  asm volatile("cp.async.wait_group %0;" :: "n"(n) : "memory")

__device__ __forceinline__ void ldsm4(uint32_t& r0, uint32_t& r1, uint32_t& r2,
                                      uint32_t& r3, uint32_t addr) {
    asm volatile("ldmatrix.sync.aligned.m8n8.x4.shared.b16 {%0,%1,%2,%3}, [%4];"
                 : "=r"(r0), "=r"(r1), "=r"(r2), "=r"(r3) : "r"(addr));
}
__device__ __forceinline__ void ldsm4t(uint32_t& r0, uint32_t& r1, uint32_t& r2,
                                       uint32_t& r3, uint32_t addr) {
    asm volatile("ldmatrix.sync.aligned.m8n8.x4.trans.shared.b16 {%0,%1,%2,%3}, [%4];"
                 : "=r"(r0), "=r"(r1), "=r"(r2), "=r"(r3) : "r"(addr));
}
__device__ __forceinline__ void mma16816h(float* c, uint32_t a0, uint32_t a1,
                                          uint32_t a2, uint32_t a3,
                                          uint32_t b0, uint32_t b1) {
    asm volatile(
        "mma.sync.aligned.m16n8k16.row.col.f32.f16.f16.f32 "
        "{%0,%1,%2,%3}, {%4,%5,%6,%7}, {%8,%9}, {%0,%1,%2,%3};"
        : "+f"(c[0]), "+f"(c[1]), "+f"(c[2]), "+f"(c[3])
        : "r"(a0), "r"(a1), "r"(a2), "r"(a3), "r"(b0), "r"(b1));
}

__device__ __forceinline__ uint32_t pack_f16x2(float lo, float hi) {
    __half2 p = __floats2half2_rn(lo, hi);
    return *(uint32_t*)&p;
}
__device__ __forceinline__ float ex2f(float x) {
    float r;
    asm("ex2.approx.f32 %0, %1;" : "=f"(r) : "f"(x));
    return r;
}

// ---------------------------------------------------------------------------
// Fused fp32 -> fp16 rounding of all 3 tensors, one launch.
// ---------------------------------------------------------------------------
#define N4_H  ((M_ * H_) / 4)
#define N4_WQ ((QKV_W * H_) / 4)
#define N4_WO ((H_ * H_) / 4)

__global__ void round3_f16(const float* __restrict__ x0, __half* __restrict__ h0,
                           const float* __restrict__ x1, __half* __restrict__ h1,
                           const float* __restrict__ x2, __half* __restrict__ h2)
{
    int i = blockIdx.x * blockDim.x + threadIdx.x;
    const float* x; __half* h;
    if (i < N4_H)                   { x = x0; h = h0; }
    else if (i < N4_H + N4_WQ)      { x = x1; h = h1; i -= N4_H; }
    else if (i < N4_H + N4_WQ + N4_WO) { x = x2; h = h2; i -= N4_H + N4_WQ; }
    else return;
    float4 v = ((const float4*)x)[i];
    ((__half2*)h)[2*i]   = __floats2half2_rn(v.x, v.y);
    ((__half2*)h)[2*i+1] = __floats2half2_rn(v.z, v.w);
}

// ---------------------------------------------------------------------------
// 1-pass fp16 mma.sync GEMM (NT), round-13 config, templated output.
// ---------------------------------------------------------------------------
#define BK      64
#define LDS_    72
#define PLANE_B (128 * LDS_ * 2)      // 18432
#define BUF_B   (2 * PLANE_B)         // 36864
#define GEMM_SMEM (2 * BUF_B)         // 73728

template <typename OutT>
__global__ __launch_bounds__(256, 2) void gemm_f16(
    const __half* __restrict__ A, const __half* __restrict__ Bw,
    OutT* __restrict__ C, int N, int K)
{
    extern __shared__ __align__(128) char smc[];
    const uint32_t sbase = (uint32_t)__cvta_generic_to_shared(smc);
    const int tid  = threadIdx.x;
    const int warp = tid >> 5, lane = tid & 31;
    const int bm = blockIdx.y * 128, bn = blockIdx.x * 128;
    const int wm = (warp >> 2) * 64;
    const int wn = (warp & 3) * 32;

    const __half* srcs[2] = { A + (size_t)bm * K, Bw + (size_t)bn * K };

    const int nch = K / BK;

    auto load_chunk = [&](int kc, int bb) {
        uint32_t sb = sbase + bb * BUF_B;
        #pragma unroll
        for (int p = 0; p < 2; p++) {
            const __half* sp = srcs[p] + kc * BK;
            uint32_t pb = sb + p * PLANE_B;
            #pragma unroll
            for (int t = 0; t < 4; t++) {
                int f = tid + t * 256;
                int r = f >> 3, j = f & 7;
                cp_async16(pb + r * (LDS_ * 2) + j * 16,
                           sp + (size_t)r * K + j * 8);
            }
        }
        CP_COMMIT();
    };

    float c[4][4][4];
    #pragma unroll
    for (int i = 0; i < 4; i++)
        #pragma unroll
        for (int j = 0; j < 4; j++)
            #pragma unroll
            for (int q = 0; q < 4; q++) c[i][j][q] = 0.f;

    load_chunk(0, 0);

    const int arow = lane & 15;
    const int ak8  = (lane >> 4) * 8;
    const int brow = (lane & 7) + ((lane >> 4) << 3);
    const int bk8  = ((lane >> 3) & 1) * 8;

    #pragma unroll 1
    for (int kc = 0; kc < nch; kc++) {
        const int bb = kc & 1;
        CP_WAIT(0);
        __syncthreads();
        if (kc + 1 < nch) load_chunk(kc + 1, bb ^ 1);

        const uint32_t sA = sbase + bb * BUF_B;
        const uint32_t sB = sA + PLANE_B;

        #pragma unroll
        for (int ks = 0; ks < 4; ks++) {
            const int k0 = ks * 16;
            uint32_t bh[4][2];
            #pragma unroll
            for (int tp = 0; tp < 2; tp++) {
                uint32_t off = (uint32_t)((wn + tp*16 + brow) * LDS_ + k0 + bk8) * 2;
                ldsm4(bh[tp*2][0], bh[tp*2][1], bh[tp*2+1][0], bh[tp*2+1][1], sB + off);
            }
            #pragma unroll
            for (int ti = 0; ti < 4; ti++) {
                uint32_t off = (uint32_t)((wm + ti*16 + arow) * LDS_ + k0 + ak8) * 2;
                uint32_t ah[4];
                ldsm4(ah[0], ah[1], ah[2], ah[3], sA + off);
                mma16816h(c[ti][0], ah[0], ah[1], ah[2], ah[3], bh[0][0], bh[0][1]);
                mma16816h(c[ti][1], ah[0], ah[1], ah[2], ah[3], bh[1][0], bh[1][1]);
                mma16816h(c[ti][2], ah[0], ah[1], ah[2], ah[3], bh[2][0], bh[2][1]);
                mma16816h(c[ti][3], ah[0], ah[1], ah[2], ah[3], bh[3][0], bh[3][1]);
            }
        }
    }

    const int cr = lane >> 2, cc = (lane & 3) * 2;
    #pragma unroll
    for (int ti = 0; ti < 4; ti++) {
        #pragma unroll
        for (int tj = 0; tj < 4; tj++) {
            int r0 = bm + wm + ti*16 + cr;
            int col = bn + wn + tj*8 + cc;
            if constexpr (sizeof(OutT) == 4) {
                *(float2*)((float*)C + (size_t)r0 * N + col) =
                    make_float2(c[ti][tj][0], c[ti][tj][1]);
                *(float2*)((float*)C + (size_t)(r0 + 8) * N + col) =
                    make_float2(c[ti][tj][2], c[ti][tj][3]);
            } else {
                *(uint32_t*)((__half*)C + (size_t)r0 * N + col) =
                    pack_f16x2(c[ti][tj][0], c[ti][tj][1]);
                *(uint32_t*)((__half*)C + (size_t)(r0 + 8) * N + col) =
                    pack_f16x2(c[ti][tj][2], c[ti][tj][3]);
            }
        }
    }
}

// ---------------------------------------------------------------------------
// Fused RoPE(Q,K) + V rearrange, fp16 in/out.
// Q scale folds 1/sqrt(96) * log2(e) so attention uses raw exp2.
// ---------------------------------------------------------------------------
#define ROPE_TOT (B_ * S_ * (NH + NKV) * (HD/2))
#define V_TOT    (B_ * S_ * NKV * (HD/4))

__global__ void rope_v_f16(const __half* __restrict__ qkv,
                           __half* __restrict__ qf, __half* __restrict__ kf,
                           __half* __restrict__ vf)
{
    int gi = blockIdx.x * blockDim.x + threadIdx.x;
    if (gi < ROPE_TOT) {
        int i = gi;
        int d    = i % (HD/2);
        int t    = i / (HD/2);
        int head = t % (NH + NKV);
        int bs   = t / (NH + NKV);
        int b    = bs / S_;
        int s    = bs % S_;

        float inv = expf(-(float)d * (logf(10000.0f) / 48.0f));
        float ang = (float)s * inv;
        float sn, cs;
        sincosf(ang, &sn, &cs);

        const __half* base = qkv + (size_t)bs * QKV_W + head * HD;
        float x1 = __half2float(base[d]);
        float x2 = __half2float(base[d + 48]);
        float y1 = x1 * cs - x2 * sn;
        float y2 = x2 * cs + x1 * sn;

        if (head < NH) {
            // 1/sqrt(96) * log2(e): softmax computed in base-2 domain
            const float scale = 0.10206207261596577f * 1.4426950408889634f;
            y1 *= scale; y2 *= scale;
            size_t idx = ((size_t)(b * NH + head) * S_ + s) * HD;
            qf[idx + d]      = __float2half_rn(y1);
            qf[idx + d + 48] = __float2half_rn(y2);
        } else {
            size_t idx = ((size_t)(b * NKV + (head - NH)) * S_ + s) * HD;
            kf[idx + d]      = __float2half_rn(y1);
            kf[idx + d + 48] = __float2half_rn(y2);
        }
    } else {
        int i = gi - ROPE_TOT;
        if (i >= V_TOT) return;
        int d4  = i % (HD/4);
        int t   = i / (HD/4);
        int kvh = t % NKV;
        int bs  = t / NKV;
        int b   = bs / S_;
        int s   = bs % S_;
        const __half* src = qkv + (size_t)bs * QKV_W + NH*HD + NKV*HD + kvh*HD + d4*4;
        size_t idx = ((size_t)(b * NKV + kvh) * S_ + s) * HD + d4*4;
        *(uint2*)(vf + idx) = *(const uint2*)src;
    }
}

// ---------------------------------------------------------------------------
// Flash attention, 1-pass fp16 mma, base-2 softmax (ex2 only, no FMUL).
// Precomputed per-lane smem address bases (add-only inner loops).
// ---------------------------------------------------------------------------
#define ALDS   104
#define QBYTES (128 * ALDS * 2)         // 26624
#define KVTILE (64 * ALDS * 2)          // 13312
#define KVBUF  (2 * KVTILE)             // 26624
#define ASTAGES 3
#define ATT_SMEM (QBYTES + ASTAGES*KVBUF)   // 106496 -> 2 CTAs/SM

__global__ __launch_bounds__(256, 2) void attn_mma(
    const __half* __restrict__ qf, const __half* __restrict__ kf,
    const __half* __restrict__ vf, __half* __restrict__ aout)
{
    extern __shared__ __align__(128) char smc[];
    const uint32_t sb  = (uint32_t)__cvta_generic_to_shared(smc);
    const uint32_t sQ  = sb;
    const uint32_t sKV = sb + QBYTES;

    const int tid  = threadIdx.x;
    const int warp = tid >> 5, lane = tid & 31;
    const int qt = (S_/128 - 1) - blockIdx.x;   // heavy tiles first
    const int bh = blockIdx.y;
    const int b  = bh >> 5, h = bh & 31, kvh = h >> 2;
    const int q0 = qt * 128;
    const int wm = warp * 16;

    const __half* qsf = qf + ((size_t)(b*NH + h) * S_ + q0) * HD;
    const __half* ksf = kf + (size_t)(b*NKV + kvh) * S_ * HD;
    const __half* vsf = vf + (size_t)(b*NKV + kvh) * S_ * HD;

    #pragma unroll
    for (int u = 0; u < 6; u++) {
        int f = tid + u * 256;
        int r = f / 12, cidx = f % 12;
        cp_async16(sQ + r * (ALDS*2) + cidx * 16, qsf + (size_t)r * HD + cidx * 8);
    }

    auto load_kv = [&](int kt, int bb) {
        uint32_t base = sKV + bb * KVBUF;
        int k0 = kt * 64;
        #pragma unroll
        for (int u = 0; u < 3; u++) {
            int f = tid + u * 256;
            int r = f / 12, cidx = f % 12;
            size_t g = (size_t)(k0 + r) * HD + cidx * 8;
            uint32_t o = r * (ALDS*2) + cidx * 16;
            cp_async16(base + 0*KVTILE + o, ksf + g);
            cp_async16(base + 1*KVTILE + o, vsf + g);
        }
        CP_COMMIT();
    };

    const int nkt = 2 * qt + 2;
    load_kv(0, 0);
    if (nkt > 1) load_kv(1, 1); else CP_COMMIT();

    const int arow = lane & 15;
    const int ak8  = (lane >> 4) * 8;
    const int brow = (lane & 7) + ((lane >> 4) << 3);
    const int bk8  = ((lane >> 3) & 1) * 8;
    const int vrow = lane & 15;
    const int vn8  = (lane >> 4) * 8;
    const int r_   = lane >> 2;
    const int c2_  = (lane & 3) * 2;

    // per-lane smem address bases (inner loops become add-only)
    const uint32_t aoff0 = (uint32_t)((wm + arow) * ALDS + ak8) * 2;
    const uint32_t boff0 = (uint32_t)(brow * ALDS + bk8) * 2;
    const uint32_t voff0 = (uint32_t)(vrow * ALDS + vn8) * 2;
    const uint32_t NSTRIDE = (uint32_t)(16 * ALDS * 2);   // 16 rows
    const uint32_t KSTRIDE = 32;                           // 16 bf16 cols

    float o[12][4];
    #pragma unroll
    for (int t = 0; t < 12; t++)
        #pragma unroll
        for (int q = 0; q < 4; q++) o[t][q] = 0.f;
    float m0 = -1e30f, m1 = -1e30f, l0 = 0.f, l1 = 0.f;

    const int row_g0 = q0 + wm + r_;
    const int wmax   = q0 + wm + 15;

    int bb = 0;
    #pragma unroll 1
    for (int kt = 0; kt < nkt; kt++) {
        const int k0 = kt * 64;
        CP_WAIT(1);
        __syncthreads();
        if (kt + 2 < nkt) {
            int nb = bb + 2; if (nb >= ASTAGES) nb -= ASTAGES;
            load_kv(kt + 2, nb);
        } else CP_COMMIT();

        if (k0 <= wmax) {
            const uint32_t sK = sKV + bb * KVBUF;
            const uint32_t sV = sK + KVTILE;

            float s[8][4];
            #pragma unroll
            for (int t = 0; t < 8; t++)
                #pragma unroll
                for (int q = 0; q < 4; q++) s[t][q] = 0.f;

            #pragma unroll
            for (int ks = 0; ks < 6; ks++) {
                uint32_t ah[4];
                ldsm4(ah[0], ah[1], ah[2], ah[3], sQ + aoff0 + ks * KSTRIDE);
                #pragma unroll
                for (int np = 0; np < 4; np++) {
                    uint32_t kh_[4];
                    ldsm4(kh_[0], kh_[1], kh_[2], kh_[3],
                          sK + boff0 + np * NSTRIDE + ks * KSTRIDE);
                    mma16816h(s[2*np],   ah[0],ah[1],ah[2],ah[3], kh_[0], kh_[1]);
                    mma16816h(s[2*np+1], ah[0],ah[1],ah[2],ah[3], kh_[2], kh_[3]);
                }
            }

            if (k0 + 63 > q0 + wm) {
                #pragma unroll
                for (int t = 0; t < 8; t++) {
                    int col = k0 + t*8 + c2_;
                    if (col     > row_g0)     s[t][0] = -1e30f;
                    if (col + 1 > row_g0)     s[t][1] = -1e30f;
                    if (col     > row_g0 + 8) s[t][2] = -1e30f;
                    if (col + 1 > row_g0 + 8) s[t][3] = -1e30f;
                }
            }

            float mx0 = -1e30f, mx1 = -1e30f;
            #pragma unroll
            for (int t = 0; t < 8; t++) {
                mx0 = fmaxf(mx0, fmaxf(s[t][0], s[t][1]));
                mx1 = fmaxf(mx1, fmaxf(s[t][2], s[t][3]));
            }
            mx0 = fmaxf(mx0, __shfl_xor_sync(0xffffffff, mx0, 1));
            mx0 = fmaxf(mx0, __shfl_xor_sync(0xffffffff, mx0, 2));
            mx1 = fmaxf(mx1, __shfl_xor_sync(0xffffffff, mx1, 1));
            mx1 = fmaxf(mx1, __shfl_xor_sync(0xffffffff, mx1, 2));

            float mn0 = fmaxf(m0, mx0), mn1 = fmaxf(m1, mx1);
            float al0 = ex2f(m0 - mn0), al1 = ex2f(m1 - mn1);
            m0 = mn0; m1 = mn1;

            float sum0 = 0.f, sum1 = 0.f;
            #pragma unroll
            for (int t = 0; t < 8; t++) {
                s[t][0] = ex2f(s[t][0] - m0);
                s[t][1] = ex2f(s[t][1] - m0);
                s[t][2] = ex2f(s[t][2] - m1);
                s[t][3] = ex2f(s[t][3] - m1);
                sum0 += s[t][0] + s[t][1];
                sum1 += s[t][2] + s[t][3];
            }
            sum0 += __shfl_xor_sync(0xffffffff, sum0, 1);
            sum0 += __shfl_xor_sync(0xffffffff, sum0, 2);
            sum1 += __shfl_xor_sync(0xffffffff, sum1, 1);
            sum1 += __shfl_xor_sync(0xffffffff, sum1, 2);
            l0 = l0 * al0 + sum0;
            l1 = l1 * al1 + sum1;

            #pragma unroll
            for (int t = 0; t < 12; t++) {
                o[t][0] *= al0; o[t][1] *= al0;
                o[t][2] *= al1; o[t][3] *= al1;
            }

            #pragma unroll
            for (int ks = 0; ks < 4; ks++) {
                const int j0 = 2*ks, j1 = 2*ks + 1;
                uint32_t ph[4];
                ph[0] = pack_f16x2(s[j0][0], s[j0][1]);
                ph[1] = pack_f16x2(s[j0][2], s[j0][3]);
                ph[2] = pack_f16x2(s[j1][0], s[j1][1]);
                ph[3] = pack_f16x2(s[j1][2], s[j1][3]);
                const uint32_t vks = sV + voff0 + ks * NSTRIDE;
                #pragma unroll
                for (int npp = 0; npp < 3; npp++) {
                    const int np = 2 * npp;
                    uint32_t vha[4], vhb[4];
                    ldsm4t(vha[0], vha[1], vha[2], vha[3], vks + np * KSTRIDE);
                    ldsm4t(vhb[0], vhb[1], vhb[2], vhb[3], vks + (np+1) * KSTRIDE);
                    mma16816h(o[2*np],   ph[0],ph[1],ph[2],ph[3], vha[0], vha[1]);
                    mma16816h(o[2*np+1], ph[0],ph[1],ph[2],ph[3], vha[2], vha[3]);
                    mma16816h(o[2*np+2], ph[0],ph[1],ph[2],ph[3], vhb[0], vhb[1]);
                    mma16816h(o[2*np+3], ph[0],ph[1],ph[2],ph[3], vhb[2], vhb[3]);
                }
            }
        }
        if (++bb == ASTAGES) bb = 0;
    }

    const float il0 = 1.f / l0, il1 = 1.f / l1;
    const size_t mrow0 = (size_t)(b * S_ + row_g0) * H_;
    const size_t mrow1 = mrow0 + 8 * (size_t)H_;
    #pragma unroll
    for (int t = 0; t < 12; t++) {
        int col = h * HD + t*8 + c2_;
        *(uint32_t*)(aout + mrow0 + col) = pack_f16x2(o[t][0]*il0, o[t][1]*il0);
        *(uint32_t*)(aout + mrow1 + col) = pack_f16x2(o[t][2]*il1, o[t][3]*il1);
    }
}

// ---------------------------------------------------------------------------

extern "C" void kernel_launch(void* const* d_in, const int* in_sizes, int n_in,
                              void* d_out, int out_size)
{
    const float* hidden = (const float*)d_in[0];
    const float* w_qkv  = (const float*)d_in[2];
    const float* w_o    = (const float*)d_in[3];
    float* out = (float*)d_out;

    __half *qkv_h, *h_f16, *wq_f16, *wo_f16, *a_f16, *q_f16, *k_f16, *v_f16;
    cudaGetSymbolAddress((void**)&qkv_h,  g_qkv_h);
    cudaGetSymbolAddress((void**)&h_f16,  g_h_f16);
    cudaGetSymbolAddress((void**)&wq_f16, g_wq_f16);
    cudaGetSymbolAddress((void**)&wo_f16, g_wo_f16);
    cudaGetSymbolAddress((void**)&a_f16,  g_a_f16);
    cudaGetSymbolAddress((void**)&q_f16,  g_q_f16);
    cudaGetSymbolAddress((void**)&k_f16,  g_k_f16);
    cudaGetSymbolAddress((void**)&v_f16,  g_v_f16);

    cudaFuncSetAttribute(gemm_f16<__half>, cudaFuncAttributeMaxDynamicSharedMemorySize, GEMM_SMEM);
    cudaFuncSetAttribute(gemm_f16<float>,  cudaFuncAttributeMaxDynamicSharedMemorySize, GEMM_SMEM);
    cudaFuncSetAttribute(attn_mma, cudaFuncAttributeMaxDynamicSharedMemorySize, ATT_SMEM);

    // 1) fused fp16 rounding (one launch)
    {
        int total = N4_H + N4_WQ + N4_WO;
        round3_f16<<<(total + 255)/256, 256>>>(hidden, h_f16, w_qkv, wq_f16,
                                               w_o, wo_f16);
    }

    // 2) QKV projection (fp16 HMMA), fp16 output
    gemm_f16<__half><<<dim3(QKV_W/128, M_/128), 256, GEMM_SMEM>>>(
        h_f16, wq_f16, qkv_h, QKV_W, H_);

    // 3) fused RoPE(Q,K) + V rearrange (log2e folded into Q scale)
    {
        int total = ROPE_TOT + V_TOT;
        rope_v_f16<<<(total + 255)/256, 256>>>(qkv_h, q_f16, k_f16, v_f16);
    }

    // 4) causal GQA flash attention (base-2 softmax)
    attn_mma<<<dim3(S_/128, B_*NH), 256, ATT_SMEM>>>(
        q_f16, k_f16, v_f16, a_f16);

    // 5) output projection (fp16 HMMA), fp32 output
    gemm_f16<float><<<dim3(H_/128, M_/128), 256, GEMM_SMEM>>>(
        a_f16, wo_f16, out, H_, H_);
}

// round 17
// speedup vs baseline: 1.0621x; 1.0216x over previous
#include <cuda_runtime.h>
#include <cuda_bf16.h>
#include <cuda_fp16.h>
#include <math.h>
#include <stdint.h>

#define B_   2
#define S_   2048
#define H_   3072
#define NH   32
#define NKV  8
#define HD   96
#define QKV_W (NH*HD + 2*NKV*HD)   // 4608
#define M_   (B_*S_)               // 4096

// ---------------- scratch (device globals: allocation-free rule) -----------
__device__ __half g_h_f16[(size_t)M_ * H_];
__device__ __half g_wq_f16[(size_t)QKV_W * H_];
__device__ __half g_wo_f16[(size_t)H_ * H_];
__device__ __half g_a_f16[(size_t)M_ * H_];
__device__ __half g_q_f16[(size_t)B_*NH*S_*HD];
__device__ __half g_k_f16[(size_t)B_*NKV*S_*HD];
__device__ __half g_v_f16[(size_t)B_*NKV*S_*HD];

// ---------------- base-target PTX helpers ----------------------------------
__device__ __forceinline__ void cp_async16(uint32_t dst, const void* src) {
    asm volatile("cp.async.cg.shared.global [%0], [%1], 16;"
                 :: "r"(dst), "l"(src) : "memory");
}
#define CP_COMMIT() asm volatile("cp.async.commit_group;" ::: "memory")
#define CP_WAIT(n)  asm volatile("cp.async.wait_group %0;" :: "n"(n) : "memory")

__device__ __forceinline__ void ldsm4(uint32_t& r0, uint32_t& r1, uint32_t& r2,
                                      uint32_t& r3, uint32_t addr) {
    asm volatile("ldmatrix.sync.aligned.m8n8.x4.shared.b16 {%0,%1,%2,%3}, [%4];"
                 : "=r"(r0), "=r"(r1), "=r"(r2), "=r"(r3) : "r"(addr));
}
__device__ __forceinline__ void ldsm4t(uint32_t& r0, uint32_t& r1, uint32_t& r2,
                                       uint32_t& r3, uint32_t addr) {
    asm volatile("ldmatrix.sync.aligned.m8n8.x4.trans.shared.b16 {%0,%1,%2,%3}, [%4];"
                 : "=r"(r0), "=r"(r1), "=r"(r2), "=r"(r3) : "r"(addr));
}
__device__ __forceinline__ void mma16816h(float* c, uint32_t a0, uint32_t a1,
                                          uint32_t a2, uint32_t a3,
                                          uint32_t b0, uint32_t b1) {
    asm volatile(
        "mma.sync.aligned.m16n8k16.row.col.f32.f16.f16.f32 "
        "{%0,%1,%2,%3}, {%4,%5,%6,%7}, {%8,%9}, {%0,%1,%2,%3};"
        : "+f"(c[0]), "+f"(c[1]), "+f"(c[2]), "+f"(c[3])
        : "r"(a0), "r"(a1), "r"(a2), "r"(a3), "r"(b0), "r"(b1));
}

__device__ __forceinline__ uint32_t pack_f16x2(float lo, float hi) {
    __half2 p = __floats2half2_rn(lo, hi);
    return *(uint32_t*)&p;
}
__device__ __forceinline__ float ex2f(float x) {
    float r;
    asm("ex2.approx.f32 %0, %1;" : "=f"(r) : "f"(x));
    return r;
}

// ---------------------------------------------------------------------------
// Fused fp32 -> fp16 rounding of all 3 input tensors, one launch.
// ---------------------------------------------------------------------------
#define N4_H  ((M_ * H_) / 4)
#define N4_WQ ((QKV_W * H_) / 4)
#define N4_WO ((H_ * H_) / 4)

__global__ void round3_f16(const float* __restrict__ x0, __half* __restrict__ h0,
                           const float* __restrict__ x1, __half* __restrict__ h1,
                           const float* __restrict__ x2, __half* __restrict__ h2)
{
    int i = blockIdx.x * blockDim.x + threadIdx.x;
    const float* x; __half* h;
    if (i < N4_H)                   { x = x0; h = h0; }
    else if (i < N4_H + N4_WQ)      { x = x1; h = h1; i -= N4_H; }
    else if (i < N4_H + N4_WQ + N4_WO) { x = x2; h = h2; i -= N4_H + N4_WQ; }
    else return;
    float4 v = ((const float4*)x)[i];
    ((__half2*)h)[2*i]   = __floats2half2_rn(v.x, v.y);
    ((__half2*)h)[2*i+1] = __floats2half2_rn(v.z, v.w);
}

// ---------------------------------------------------------------------------
// GEMM core (round-13 config). Two epilogues: plain OutT, or qkv head-major
// scatter into the q/k/v planes (pre-rope values).
// ---------------------------------------------------------------------------
#define BK      64
#define LDS_    72
#define PLANE_B (128 * LDS_ * 2)      // 18432
#define BUF_B   (2 * PLANE_B)         // 36864
#define GEMM_SMEM (2 * BUF_B)         // 73728

__device__ __forceinline__ void store_qkv(int row, int col, uint32_t val,
                                          __half* q, __half* k, __half* v)
{
    int b = row >> 11, s = row & (S_ - 1);
    if (col < NH * HD) {
        int h = col / HD, d = col - h * HD;
        *(uint32_t*)(q + ((size_t)(b * NH + h) * S_ + s) * HD + d) = val;
    } else if (col < (NH + NKV) * HD) {
        int c2 = col - NH * HD;
        int h = c2 / HD, d = c2 - h * HD;
        *(uint32_t*)(k + ((size_t)(b * NKV + h) * S_ + s) * HD + d) = val;
    } else {
        int c2 = col - (NH + NKV) * HD;
        int h = c2 / HD, d = c2 - h * HD;
        *(uint32_t*)(v + ((size_t)(b * NKV + h) * S_ + s) * HD + d) = val;
    }
}

template <int MODE>   // 0: fp32 C, 1: qkv scatter
__global__ __launch_bounds__(256, 2) void gemm_f16(
    const __half* __restrict__ A, const __half* __restrict__ Bw,
    float* __restrict__ C,
    __half* __restrict__ qp, __half* __restrict__ kp, __half* __restrict__ vp,
    int N, int K)
{
    extern __shared__ __align__(128) char smc[];
    const uint32_t sbase = (uint32_t)__cvta_generic_to_shared(smc);
    const int tid  = threadIdx.x;
    const int warp = tid >> 5, lane = tid & 31;
    const int bm = blockIdx.y * 128, bn = blockIdx.x * 128;
    const int wm = (warp >> 2) * 64;
    const int wn = (warp & 3) * 32;

    const __half* srcs[2] = { A + (size_t)bm * K, Bw + (size_t)bn * K };

    const int nch = K / BK;

    auto load_chunk = [&](int kc, int bb) {
        uint32_t sb = sbase + bb * BUF_B;
        #pragma unroll
        for (int p = 0; p < 2; p++) {
            const __half* sp = srcs[p] + kc * BK;
            uint32_t pb = sb + p * PLANE_B;
            #pragma unroll
            for (int t = 0; t < 4; t++) {
                int f = tid + t * 256;
                int r = f >> 3, j = f & 7;
                cp_async16(pb + r * (LDS_ * 2) + j * 16,
                           sp + (size_t)r * K + j * 8);
            }
        }
        CP_COMMIT();
    };

    float c[4][4][4];
    #pragma unroll
    for (int i = 0; i < 4; i++)
        #pragma unroll
        for (int j = 0; j < 4; j++)
            #pragma unroll
            for (int q = 0; q < 4; q++) c[i][j][q] = 0.f;

    load_chunk(0, 0);

    const int arow = lane & 15;
    const int ak8  = (lane >> 4) * 8;
    const int brow = (lane & 7) + ((lane >> 4) << 3);
    const int bk8  = ((lane >> 3) & 1) * 8;

    #pragma unroll 1
    for (int kc = 0; kc < nch; kc++) {
        const int bb = kc & 1;
        CP_WAIT(0);
        __syncthreads();
        if (kc + 1 < nch) load_chunk(kc + 1, bb ^ 1);

        const uint32_t sA = sbase + bb * BUF_B;
        const uint32_t sB = sA + PLANE_B;

        #pragma unroll
        for (int ks = 0; ks < 4; ks++) {
            const int k0 = ks * 16;
            uint32_t bh[4][2];
            #pragma unroll
            for (int tp = 0; tp < 2; tp++) {
                uint32_t off = (uint32_t)((wn + tp*16 + brow) * LDS_ + k0 + bk8) * 2;
                ldsm4(bh[tp*2][0], bh[tp*2][1], bh[tp*2+1][0], bh[tp*2+1][1], sB + off);
            }
            #pragma unroll
            for (int ti = 0; ti < 4; ti++) {
                uint32_t off = (uint32_t)((wm + ti*16 + arow) * LDS_ + k0 + ak8) * 2;
                uint32_t ah[4];
                ldsm4(ah[0], ah[1], ah[2], ah[3], sA + off);
                mma16816h(c[ti][0], ah[0], ah[1], ah[2], ah[3], bh[0][0], bh[0][1]);
                mma16816h(c[ti][1], ah[0], ah[1], ah[2], ah[3], bh[1][0], bh[1][1]);
                mma16816h(c[ti][2], ah[0], ah[1], ah[2], ah[3], bh[2][0], bh[2][1]);
                mma16816h(c[ti][3], ah[0], ah[1], ah[2], ah[3], bh[3][0], bh[3][1]);
            }
        }
    }

    const int cr = lane >> 2, cc = (lane & 3) * 2;
    #pragma unroll
    for (int ti = 0; ti < 4; ti++) {
        #pragma unroll
        for (int tj = 0; tj < 4; tj++) {
            int r0 = bm + wm + ti*16 + cr;
            int col = bn + wn + tj*8 + cc;
            if constexpr (MODE == 0) {
                *(float2*)(C + (size_t)r0 * N + col) =
                    make_float2(c[ti][tj][0], c[ti][tj][1]);
                *(float2*)(C + (size_t)(r0 + 8) * N + col) =
                    make_float2(c[ti][tj][2], c[ti][tj][3]);
            } else {
                store_qkv(r0,     col, pack_f16x2(c[ti][tj][0], c[ti][tj][1]), qp, kp, vp);
                store_qkv(r0 + 8, col, pack_f16x2(c[ti][tj][2], c[ti][tj][3]), qp, kp, vp);
            }
        }
    }
}

// ---------------------------------------------------------------------------
// In-place RoPE on head-major q/k planes, 16B-vectorized.
// Q gets 1/sqrt(96)*log2(e) folded (base-2 softmax downstream).
// ---------------------------------------------------------------------------
#define QROWS (B_ * NH * S_)     // 131072
#define KROWS (B_ * NKV * S_)    // 32768
#define ROPE_THREADS ((QROWS + KROWS) * 6)

__global__ void rope_f16(__half* __restrict__ qf, __half* __restrict__ kf)
{
    int gi = blockIdx.x * blockDim.x + threadIdx.x;
    __half* base; int row, c8; float scale;
    if (gi < QROWS * 6) {
        row = gi / 6; c8 = gi % 6; base = qf;
        scale = 0.10206207261596577f * 1.4426950408889634f;
    } else {
        gi -= QROWS * 6;
        if (gi >= KROWS * 6) return;
        row = gi / 6; c8 = gi % 6; base = kf;
        scale = 1.0f;
    }
    const int s  = row & (S_ - 1);
    const int d0 = c8 * 8;
    __half* p = base + (size_t)row * HD;

    __half hlo[8], hhi[8];
    *(uint4*)hlo = *(const uint4*)(p + d0);
    *(uint4*)hhi = *(const uint4*)(p + d0 + 48);

    #pragma unroll
    for (int j = 0; j < 8; j++) {
        int d = d0 + j;
        float inv = expf(-(float)d * (logf(10000.0f) / 48.0f));
        float ang = (float)s * inv;
        float sn, cs;
        sincosf(ang, &sn, &cs);
        float x1 = __half2float(hlo[j]);
        float x2 = __half2float(hhi[j]);
        hlo[j] = __float2half_rn((x1 * cs - x2 * sn) * scale);
        hhi[j] = __float2half_rn((x2 * cs + x1 * sn) * scale);
    }
    *(uint4*)(p + d0)      = *(uint4*)hlo;
    *(uint4*)(p + d0 + 48) = *(uint4*)hhi;
}

// ---------------------------------------------------------------------------
// Flash attention, 1-pass fp16 mma, base-2 softmax (round-16 config).
// ---------------------------------------------------------------------------
#define ALDS   104
#define QBYTES (128 * ALDS * 2)         // 26624
#define KVTILE (64 * ALDS * 2)          // 13312
#define KVBUF  (2 * KVTILE)             // 26624
#define ASTAGES 3
#define ATT_SMEM (QBYTES + ASTAGES*KVBUF)   // 106496 -> 2 CTAs/SM

__global__ __launch_bounds__(256, 2) void attn_mma(
    const __half* __restrict__ qf, const __half* __restrict__ kf,
    const __half* __restrict__ vf, __half* __restrict__ aout)
{
    extern __shared__ __align__(128) char smc[];
    const uint32_t sb  = (uint32_t)__cvta_generic_to_shared(smc);
    const uint32_t sQ  = sb;
    const uint32_t sKV = sb + QBYTES;

    const int tid  = threadIdx.x;
    const int warp = tid >> 5, lane = tid & 31;
    const int qt = (S_/128 - 1) - blockIdx.x;   // heavy tiles first
    const int bh = blockIdx.y;
    const int b  = bh >> 5, h = bh & 31, kvh = h >> 2;
    const int q0 = qt * 128;
    const int wm = warp * 16;

    const __half* qsf = qf + ((size_t)(b*NH + h) * S_ + q0) * HD;
    const __half* ksf = kf + (size_t)(b*NKV + kvh) * S_ * HD;
    const __half* vsf = vf + (size_t)(b*NKV + kvh) * S_ * HD;

    #pragma unroll
    for (int u = 0; u < 6; u++) {
        int f = tid + u * 256;
        int r = f / 12, cidx = f % 12;
        cp_async16(sQ + r * (ALDS*2) + cidx * 16, qsf + (size_t)r * HD + cidx * 8);
    }

    auto load_kv = [&](int kt, int bb) {
        uint32_t base = sKV + bb * KVBUF;
        int k0 = kt * 64;
        #pragma unroll
        for (int u = 0; u < 3; u++) {
            int f = tid + u * 256;
            int r = f / 12, cidx = f % 12;
            size_t g = (size_t)(k0 + r) * HD + cidx * 8;
            uint32_t o = r * (ALDS*2) + cidx * 16;
            cp_async16(base + 0*KVTILE + o, ksf + g);
            cp_async16(base + 1*KVTILE + o, vsf + g);
        }
        CP_COMMIT();
    };

    const int nkt = 2 * qt + 2;
    load_kv(0, 0);
    if (nkt > 1) load_kv(1, 1); else CP_COMMIT();

    const int arow = lane & 15;
    const int ak8  = (lane >> 4) * 8;
    const int brow = (lane & 7) + ((lane >> 4) << 3);
    const int bk8  = ((lane >> 3) & 1) * 8;
    const int vrow = lane & 15;
    const int vn8  = (lane >> 4) * 8;
    const int r_   = lane >> 2;
    const int c2_  = (lane & 3) * 2;

    const uint32_t aoff0 = (uint32_t)((wm + arow) * ALDS + ak8) * 2;
    const uint32_t boff0 = (uint32_t)(brow * ALDS + bk8) * 2;
    const uint32_t voff0 = (uint32_t)(vrow * ALDS + vn8) * 2;
    const uint32_t NSTRIDE = (uint32_t)(16 * ALDS * 2);
    const uint32_t KSTRIDE = 32;

    float o[12][4];
    #pragma unroll
    for (int t = 0; t < 12; t++)
        #pragma unroll
        for (int q = 0; q < 4; q++) o[t][q] = 0.f;
    float m0 = -1e30f, m1 = -1e30f, l0 = 0.f, l1 = 0.f;

    const int row_g0 = q0 + wm + r_;
    const int wmax   = q0 + wm + 15;

    int bb = 0;
    #pragma unroll 1
    for (int kt = 0; kt < nkt; kt++) {
        const int k0 = kt * 64;
        CP_WAIT(1);
        __syncthreads();
        if (kt + 2 < nkt) {
            int nb = bb + 2; if (nb >= ASTAGES) nb -= ASTAGES;
            load_kv(kt + 2, nb);
        } else CP_COMMIT();

        if (k0 <= wmax) {
            const uint32_t sK = sKV + bb * KVBUF;
            const uint32_t sV = sK + KVTILE;

            float s[8][4];
            #pragma unroll
            for (int t = 0; t < 8; t++)
                #pragma unroll
                for (int q = 0; q < 4; q++) s[t][q] = 0.f;

            #pragma unroll
            for (int ks = 0; ks < 6; ks++) {
                uint32_t ah[4];
                ldsm4(ah[0], ah[1], ah[2], ah[3], sQ + aoff0 + ks * KSTRIDE);
                #pragma unroll
                for (int np = 0; np < 4; np++) {
                    uint32_t kh_[4];
                    ldsm4(kh_[0], kh_[1], kh_[2], kh_[3],
                          sK + boff0 + np * NSTRIDE + ks * KSTRIDE);
                    mma16816h(s[2*np],   ah[0],ah[1],ah[2],ah[3], kh_[0], kh_[1]);
                    mma16816h(s[2*np+1], ah[0],ah[1],ah[2],ah[3], kh_[2], kh_[3]);
                }
            }

            if (k0 + 63 > q0 + wm) {
                #pragma unroll
                for (int t = 0; t < 8; t++) {
                    int col = k0 + t*8 + c2_;
                    if (col     > row_g0)     s[t][0] = -1e30f;
                    if (col + 1 > row_g0)     s[t][1] = -1e30f;
                    if (col     > row_g0 + 8) s[t][2] = -1e30f;
                    if (col + 1 > row_g0 + 8) s[t][3] = -1e30f;
                }
            }

            float mx0 = -1e30f, mx1 = -1e30f;
            #pragma unroll
            for (int t = 0; t < 8; t++) {
                mx0 = fmaxf(mx0, fmaxf(s[t][0], s[t][1]));
                mx1 = fmaxf(mx1, fmaxf(s[t][2], s[t][3]));
            }
            mx0 = fmaxf(mx0, __shfl_xor_sync(0xffffffff, mx0, 1));
            mx0 = fmaxf(mx0, __shfl_xor_sync(0xffffffff, mx0, 2));
            mx1 = fmaxf(mx1, __shfl_xor_sync(0xffffffff, mx1, 1));
            mx1 = fmaxf(mx1, __shfl_xor_sync(0xffffffff, mx1, 2));

            float mn0 = fmaxf(m0, mx0), mn1 = fmaxf(m1, mx1);
            float al0 = ex2f(m0 - mn0), al1 = ex2f(m1 - mn1);
            m0 = mn0; m1 = mn1;

            float sum0 = 0.f, sum1 = 0.f;
            #pragma unroll
            for (int t = 0; t < 8; t++) {
                s[t][0] = ex2f(s[t][0] - m0);
                s[t][1] = ex2f(s[t][1] - m0);
                s[t][2] = ex2f(s[t][2] - m1);
                s[t][3] = ex2f(s[t][3] - m1);
                sum0 += s[t][0] + s[t][1];
                sum1 += s[t][2] + s[t][3];
            }
            sum0 += __shfl_xor_sync(0xffffffff, sum0, 1);
            sum0 += __shfl_xor_sync(0xffffffff, sum0, 2);
            sum1 += __shfl_xor_sync(0xffffffff, sum1, 1);
            sum1 += __shfl_xor_sync(0xffffffff, sum1, 2);
            l0 = l0 * al0 + sum0;
            l1 = l1 * al1 + sum1;

            #pragma unroll
            for (int t = 0; t < 12; t++) {
                o[t][0] *= al0; o[t][1] *= al0;
                o[t][2] *= al1; o[t][3] *= al1;
            }

            #pragma unroll
            for (int ks = 0; ks < 4; ks++) {
                const int j0 = 2*ks, j1 = 2*ks + 1;
                uint32_t ph[4];
                ph[0] = pack_f16x2(s[j0][0], s[j0][1]);
                ph[1] = pack_f16x2(s[j0][2], s[j0][3]);
                ph[2] = pack_f16x2(s[j1][0], s[j1][1]);
                ph[3] = pack_f16x2(s[j1][2], s[j1][3]);
                const uint32_t vks = sV + voff0 + ks * NSTRIDE;
                #pragma unroll
                for (int npp = 0; npp < 3; npp++) {
                    const int np = 2 * npp;
                    uint32_t vha[4], vhb[4];
                    ldsm4t(vha[0], vha[1], vha[2], vha[3], vks + np * KSTRIDE);
                    ldsm4t(vhb[0], vhb[1], vhb[2], vhb[3], vks + (np+1) * KSTRIDE);
                    mma16816h(o[2*np],   ph[0],ph[1],ph[2],ph[3], vha[0], vha[1]);
                    mma16816h(o[2*np+1], ph[0],ph[1],ph[2],ph[3], vha[2], vha[3]);
                    mma16816h(o[2*np+2], ph[0],ph[1],ph[2],ph[3], vhb[0], vhb[1]);
                    mma16816h(o[2*np+3], ph[0],ph[1],ph[2],ph[3], vhb[2], vhb[3]);
                }
            }
        }
        if (++bb == ASTAGES) bb = 0;
    }

    const float il0 = 1.f / l0, il1 = 1.f / l1;
    const size_t mrow0 = (size_t)(b * S_ + row_g0) * H_;
    const size_t mrow1 = mrow0 + 8 * (size_t)H_;
    #pragma unroll
    for (int t = 0; t < 12; t++) {
        int col = h * HD + t*8 + c2_;
        *(uint32_t*)(aout + mrow0 + col) = pack_f16x2(o[t][0]*il0, o[t][1]*il0);
        *(uint32_t*)(aout + mrow1 + col) = pack_f16x2(o[t][2]*il1, o[t][3]*il1);
    }
}

// ---------------------------------------------------------------------------

extern "C" void kernel_launch(void* const* d_in, const int* in_sizes, int n_in,
                              void* d_out, int out_size)
{
    const float* hidden = (const float*)d_in[0];
    const float* w_qkv  = (const float*)d_in[2];
    const float* w_o    = (const float*)d_in[3];
    float* out = (float*)d_out;

    __half *h_f16, *wq_f16, *wo_f16, *a_f16, *q_f16, *k_f16, *v_f16;
    cudaGetSymbolAddress((void**)&h_f16,  g_h_f16);
    cudaGetSymbolAddress((void**)&wq_f16, g_wq_f16);
    cudaGetSymbolAddress((void**)&wo_f16, g_wo_f16);
    cudaGetSymbolAddress((void**)&a_f16,  g_a_f16);
    cudaGetSymbolAddress((void**)&q_f16,  g_q_f16);
    cudaGetSymbolAddress((void**)&k_f16,  g_k_f16);
    cudaGetSymbolAddress((void**)&v_f16,  g_v_f16);

    cudaFuncSetAttribute(gemm_f16<0>, cudaFuncAttributeMaxDynamicSharedMemorySize, GEMM_SMEM);
    cudaFuncSetAttribute(gemm_f16<1>, cudaFuncAttributeMaxDynamicSharedMemorySize, GEMM_SMEM);
    cudaFuncSetAttribute(attn_mma, cudaFuncAttributeMaxDynamicSharedMemorySize, ATT_SMEM);

    // 1) fused fp16 rounding (one launch)
    {
        int total = N4_H + N4_WQ + N4_WO;
        round3_f16<<<(total + 255)/256, 256>>>(hidden, h_f16, w_qkv, wq_f16,
                                               w_o, wo_f16);
    }

    // 2) QKV projection (fp16 HMMA), scattering into head-major q/k/v planes
    gemm_f16<1><<<dim3(QKV_W/128, M_/128), 256, GEMM_SMEM>>>(
        h_f16, wq_f16, nullptr, q_f16, k_f16, v_f16, QKV_W, H_);

    // 3) in-place vectorized RoPE on q/k planes (log2e folded into Q)
    rope_f16<<<(ROPE_THREADS + 255)/256, 256>>>(q_f16, k_f16);

    // 4) causal GQA flash attention (base-2 softmax)
    attn_mma<<<dim3(S_/128, B_*NH), 256, ATT_SMEM>>>(
        q_f16, k_f16, v_f16, a_f16);

    // 5) output projection (fp16 HMMA), fp32 output
    gemm_f16<0><<<dim3(H_/128, M_/128), 256, GEMM_SMEM>>>(
        a_f16, wo_f16, out, nullptr, nullptr, nullptr, H_, H_);
}